// round 7
// baseline (speedup 1.0000x reference)
#include <cuda_runtime.h>
#include <cuda_bf16.h>

// AllReduce(sum over tp=8) + residual add + RMSNorm, fused single pass.
// R7: 2 tokens per CTA, ONE barrier per token pair. Token B's 18 loads are
// issued between token A's warp-reduce and the shared barrier -> the
// pre-barrier region is load-dense for 2 tokens per barrier; reduce/rsqrt
// overhead per byte halves. Mainloop keeps R6's dual-stream interleave.
// Register clamp (512,3) ~ 40 regs, occ ~75% (past the knee of the
// measured occ->DRAM curve: 75%->85.8, 97%->86.9 with interleave).

constexpr int TOKENS = 4096;
constexpr int HIDDEN = 4096;
constexpr int TP     = 8;
constexpr int H4     = HIDDEN / 4;        // 1024 float4 per row
constexpr int NTHREADS = 512;
constexpr int NWARPS  = NTHREADS / 32;    // 16
constexpr int GRID   = TOKENS / 2;        // 2048 CTAs, 2 tokens each
constexpr float EPS = 1e-6f;

__device__ __forceinline__ void load_acc_token(
    const float4* __restrict__ input, const float4* __restrict__ residual,
    size_t row_off, size_t tp_stride, int idx0, int idx1,
    float4& a0, float4& a1, float& ss)
{
    const float4* __restrict__ res_row = residual + row_off;
    const float4* __restrict__ in_row  = input + row_off;

    a0 = __ldcs(&res_row[idx0]);
    a1 = __ldcs(&res_row[idx1]);

    #pragma unroll
    for (int t = 0; t < TP; t++) {
        const size_t base = (size_t)t * tp_stride;
        float4 v0 = __ldcs(&in_row[base + idx0]);
        float4 v1 = __ldcs(&in_row[base + idx1]);
        a0.x += v0.x; a0.y += v0.y; a0.z += v0.z; a0.w += v0.w;
        a1.x += v1.x; a1.y += v1.y; a1.z += v1.z; a1.w += v1.w;
    }

    ss = 0.0f;
    ss = fmaf(a0.x, a0.x, ss); ss = fmaf(a0.y, a0.y, ss);
    ss = fmaf(a0.z, a0.z, ss); ss = fmaf(a0.w, a0.w, ss);
    ss = fmaf(a1.x, a1.x, ss); ss = fmaf(a1.y, a1.y, ss);
    ss = fmaf(a1.z, a1.z, ss); ss = fmaf(a1.w, a1.w, ss);
}

__global__ __launch_bounds__(NTHREADS, 3) void allreduce_rmsnorm_kernel(
    const float4* __restrict__ input,     // [TP, TOKENS, H4]
    const float4* __restrict__ residual,  // [TOKENS, H4]
    const float4* __restrict__ weight,    // [H4]
    float4* __restrict__ out_norm,        // [TOKENS, H4]
    float4* __restrict__ out_hidden)      // [TOKENS, H4]
{
    const int tid   = threadIdx.x;
    const int lane  = tid & 31;
    const int wid   = tid >> 5;
    const int idx0  = tid;
    const int idx1  = tid + NTHREADS;

    const size_t tp_stride = (size_t)TOKENS * H4;
    const int tokenA = blockIdx.x * 2;
    const int tokenB = tokenA + 1;
    const size_t offA = (size_t)tokenA * H4;
    const size_t offB = (size_t)tokenB * H4;

    __shared__ float warp_ssA[NWARPS];
    __shared__ float warp_ssB[NWARPS];

    // ---- Token A: load + accumulate ----
    float4 aA0, aA1; float ssA;
    load_acc_token(input, residual, offA, tp_stride, idx0, idx1, aA0, aA1, ssA);

    // Hidden-stream A store (independent of rstd).
    __stcs(&out_hidden[offA + idx0], aA0);
    __stcs(&out_hidden[offA + idx1], aA1);

    // Warp-reduce A -> smem (no barrier yet).
    #pragma unroll
    for (int off = 16; off > 0; off >>= 1)
        ssA += __shfl_xor_sync(0xFFFFFFFFu, ssA, off);
    if (lane == 0) warp_ssA[wid] = ssA;

    // ---- Token B: load + accumulate (fills the pre-barrier window) ----
    float4 aB0, aB1; float ssB;
    load_acc_token(input, residual, offB, tp_stride, idx0, idx1, aB0, aB1, ssB);

    __stcs(&out_hidden[offB + idx0], aB0);
    __stcs(&out_hidden[offB + idx1], aB1);

    #pragma unroll
    for (int off = 16; off > 0; off >>= 1)
        ssB += __shfl_xor_sync(0xFFFFFFFFu, ssB, off);
    if (lane == 0) warp_ssB[wid] = ssB;

    // ---- Single barrier for both tokens ----
    __syncthreads();

    float totA = 0.0f, totB = 0.0f;
    #pragma unroll
    for (int w = 0; w < NWARPS; w++) {
        totA += warp_ssA[w];
        totB += warp_ssB[w];
    }
    const float rstdA = rsqrtf(totA * (1.0f / (float)HIDDEN) + EPS);
    const float rstdB = rsqrtf(totB * (1.0f / (float)HIDDEN) + EPS);

    // ---- Epilogues: normalized outputs ----
    const float4 w0 = __ldg(&weight[idx0]);
    const float4 w1 = __ldg(&weight[idx1]);

    float4 n;
    n.x = aA0.x * rstdA * w0.x; n.y = aA0.y * rstdA * w0.y;
    n.z = aA0.z * rstdA * w0.z; n.w = aA0.w * rstdA * w0.w;
    __stcs(&out_norm[offA + idx0], n);
    n.x = aA1.x * rstdA * w1.x; n.y = aA1.y * rstdA * w1.y;
    n.z = aA1.z * rstdA * w1.z; n.w = aA1.w * rstdA * w1.w;
    __stcs(&out_norm[offA + idx1], n);

    n.x = aB0.x * rstdB * w0.x; n.y = aB0.y * rstdB * w0.y;
    n.z = aB0.z * rstdB * w0.z; n.w = aB0.w * rstdB * w0.w;
    __stcs(&out_norm[offB + idx0], n);
    n.x = aB1.x * rstdB * w1.x; n.y = aB1.y * rstdB * w1.y;
    n.z = aB1.z * rstdB * w1.z; n.w = aB1.w * rstdB * w1.w;
    __stcs(&out_norm[offB + idx1], n);
}

extern "C" void kernel_launch(void* const* d_in, const int* in_sizes, int n_in,
                              void* d_out, int out_size)
{
    const float4* input    = (const float4*)d_in[0];
    const float4* residual = (const float4*)d_in[1];
    const float4* weight   = (const float4*)d_in[2];

    float4* out_norm   = (float4*)d_out;
    float4* out_hidden = (float4*)((float*)d_out + (size_t)TOKENS * HIDDEN);

    allreduce_rmsnorm_kernel<<<GRID, NTHREADS>>>(
        input, residual, weight, out_norm, out_hidden);
}

// round 8
// speedup vs baseline: 1.0763x; 1.0763x over previous
#include <cuda_runtime.h>
#include <cuda_bf16.h>

// AllReduce(sum over tp=8) + residual add + RMSNorm, fused single pass.
// R8 = R6 (best: 102.9us kernel, DRAM 86.9%) + weight-load hoist before the
// barrier (removes two L2-latency loads from the post-barrier critical path).
// R7's 2-token variant regressed (regs 40, MLP collapse, DRAM 79%) -> reverted.
// Structure: 512 thr, 32-reg clamp (4 CTAs/SM, ~97% occ), one CTA per token,
// dual-stream interleaved TP mainloop, hidden-stream store pre-barrier,
// single __syncthreads, redundant per-thread final reduce.

constexpr int TOKENS = 4096;
constexpr int HIDDEN = 4096;
constexpr int TP     = 8;
constexpr int H4     = HIDDEN / 4;        // 1024 float4 per row
constexpr int NTHREADS = 512;
constexpr int NWARPS  = NTHREADS / 32;    // 16
constexpr float EPS = 1e-6f;

__global__ __launch_bounds__(NTHREADS, 4) void allreduce_rmsnorm_kernel(
    const float4* __restrict__ input,     // [TP, TOKENS, H4]
    const float4* __restrict__ residual,  // [TOKENS, H4]
    const float4* __restrict__ weight,    // [H4]
    float4* __restrict__ out_norm,        // [TOKENS, H4]
    float4* __restrict__ out_hidden)      // [TOKENS, H4]
{
    const int token = blockIdx.x;
    const int tid   = threadIdx.x;
    const int lane  = tid & 31;
    const int wid   = tid >> 5;

    const size_t row_off   = (size_t)token * H4;
    const size_t tp_stride = (size_t)TOKENS * H4;

    const int idx0 = tid;                 // chunk 0 element
    const int idx1 = tid + NTHREADS;      // chunk 1 element

    const float4* __restrict__ res_row = residual + row_off;
    const float4* __restrict__ in_row  = input + row_off;

    // Two independent accumulation streams, loads interleaved.
    float4 a0 = __ldcs(&res_row[idx0]);
    float4 a1 = __ldcs(&res_row[idx1]);

    #pragma unroll
    for (int t = 0; t < TP; t++) {
        const size_t base = (size_t)t * tp_stride;
        float4 v0 = __ldcs(&in_row[base + idx0]);
        float4 v1 = __ldcs(&in_row[base + idx1]);
        a0.x += v0.x; a0.y += v0.y; a0.z += v0.z; a0.w += v0.w;
        a1.x += v1.x; a1.y += v1.y; a1.z += v1.z; a1.w += v1.w;
    }

    float ss = 0.0f;
    ss = fmaf(a0.x, a0.x, ss); ss = fmaf(a0.y, a0.y, ss);
    ss = fmaf(a0.z, a0.z, ss); ss = fmaf(a0.w, a0.w, ss);
    ss = fmaf(a1.x, a1.x, ss); ss = fmaf(a1.y, a1.y, ss);
    ss = fmaf(a1.z, a1.z, ss); ss = fmaf(a1.w, a1.w, ss);

    // Residual-stream output does not depend on rstd: store before the
    // barrier so DRAM stays busy through the reduce window.
    __stcs(&out_hidden[row_off + idx0], a0);
    __stcs(&out_hidden[row_off + idx1], a1);

    // Prefetch weight (L2-hit, reused by all CTAs) before the barrier so the
    // post-barrier epilogue doesn't wait on it.
    const float4 w0 = __ldg(&weight[idx0]);
    const float4 w1 = __ldg(&weight[idx1]);

    // Warp reduce -> smem -> single barrier -> redundant per-thread finish.
    #pragma unroll
    for (int off = 16; off > 0; off >>= 1)
        ss += __shfl_xor_sync(0xFFFFFFFFu, ss, off);

    __shared__ float warp_ss[NWARPS];
    if (lane == 0) warp_ss[wid] = ss;
    __syncthreads();

    float tot = 0.0f;
    #pragma unroll
    for (int w = 0; w < NWARPS; w++)
        tot += warp_ss[w];
    const float rstd = rsqrtf(tot * (1.0f / (float)HIDDEN) + EPS);

    // Normalized output.
    float4 n0, n1;
    n0.x = a0.x * rstd * w0.x; n0.y = a0.y * rstd * w0.y;
    n0.z = a0.z * rstd * w0.z; n0.w = a0.w * rstd * w0.w;
    n1.x = a1.x * rstd * w1.x; n1.y = a1.y * rstd * w1.y;
    n1.z = a1.z * rstd * w1.z; n1.w = a1.w * rstd * w1.w;
    __stcs(&out_norm[row_off + idx0], n0);
    __stcs(&out_norm[row_off + idx1], n1);
}

extern "C" void kernel_launch(void* const* d_in, const int* in_sizes, int n_in,
                              void* d_out, int out_size)
{
    const float4* input    = (const float4*)d_in[0];
    const float4* residual = (const float4*)d_in[1];
    const float4* weight   = (const float4*)d_in[2];

    float4* out_norm   = (float4*)d_out;
    float4* out_hidden = (float4*)((float*)d_out + (size_t)TOKENS * HIDDEN);

    allreduce_rmsnorm_kernel<<<TOKENS, NTHREADS>>>(
        input, residual, weight, out_norm, out_hidden);
}

// round 9
// speedup vs baseline: 1.0805x; 1.0039x over previous
#include <cuda_runtime.h>
#include <cuda_bf16.h>

// AllReduce(sum over tp=8) + residual add + RMSNorm, fused single pass.
// R9: probe 1024 threads / CHUNKS=1. One accumulator float4 (4 regs, vs 8 in
// R6's dual-stream) frees reg budget for a deeper in-flight LDG.128 window
// under the same 32-reg clamp; __launch_bounds__(1024,2) keeps 64 warps/SM.
// Everything else identical to R6 (best: 102.9us kernel, DRAM 86.9%):
// streaming loads/stores, hidden-store before the single barrier, redundant
// per-thread final reduce, weight loaded after the barrier (R8 hoist reverted
// -- measured neutral/negative).

constexpr int TOKENS = 4096;
constexpr int HIDDEN = 4096;
constexpr int TP     = 8;
constexpr int H4     = HIDDEN / 4;        // 1024 float4 per row
constexpr int NTHREADS = 1024;
constexpr int NWARPS  = NTHREADS / 32;    // 32
constexpr float EPS = 1e-6f;

__global__ __launch_bounds__(NTHREADS, 2) void allreduce_rmsnorm_kernel(
    const float4* __restrict__ input,     // [TP, TOKENS, H4]
    const float4* __restrict__ residual,  // [TOKENS, H4]
    const float4* __restrict__ weight,    // [H4]
    float4* __restrict__ out_norm,        // [TOKENS, H4]
    float4* __restrict__ out_hidden)      // [TOKENS, H4]
{
    const int token = blockIdx.x;
    const int tid   = threadIdx.x;        // == element index, H4 = NTHREADS
    const int lane  = tid & 31;
    const int wid   = tid >> 5;

    const size_t row_off   = (size_t)token * H4;
    const size_t tp_stride = (size_t)TOKENS * H4;

    const float4* __restrict__ in_row = input + row_off;

    // Single accumulation stream: 9 independent streaming loads.
    float4 a = __ldcs(&residual[row_off + tid]);

    #pragma unroll
    for (int t = 0; t < TP; t++) {
        float4 v = __ldcs(&in_row[(size_t)t * tp_stride + tid]);
        a.x += v.x; a.y += v.y; a.z += v.z; a.w += v.w;
    }

    float ss = 0.0f;
    ss = fmaf(a.x, a.x, ss); ss = fmaf(a.y, a.y, ss);
    ss = fmaf(a.z, a.z, ss); ss = fmaf(a.w, a.w, ss);

    // Residual-stream output does not depend on rstd: store before the
    // barrier so DRAM stays busy through the reduce window.
    __stcs(&out_hidden[row_off + tid], a);

    // Warp reduce -> smem -> single barrier -> redundant per-thread finish.
    #pragma unroll
    for (int off = 16; off > 0; off >>= 1)
        ss += __shfl_xor_sync(0xFFFFFFFFu, ss, off);

    __shared__ float warp_ss[NWARPS];
    if (lane == 0) warp_ss[wid] = ss;
    __syncthreads();

    float tot = 0.0f;
    #pragma unroll
    for (int w = 0; w < NWARPS; w++)
        tot += warp_ss[w];
    const float rstd = rsqrtf(tot * (1.0f / (float)HIDDEN) + EPS);

    // Normalized output; weight is 16KB, reused by all CTAs -> L2-cached.
    const float4 w = __ldg(&weight[tid]);
    float4 n;
    n.x = a.x * rstd * w.x;
    n.y = a.y * rstd * w.y;
    n.z = a.z * rstd * w.z;
    n.w = a.w * rstd * w.w;
    __stcs(&out_norm[row_off + tid], n);
}

extern "C" void kernel_launch(void* const* d_in, const int* in_sizes, int n_in,
                              void* d_out, int out_size)
{
    const float4* input    = (const float4*)d_in[0];
    const float4* residual = (const float4*)d_in[1];
    const float4* weight   = (const float4*)d_in[2];

    float4* out_norm   = (float4*)d_out;
    float4* out_hidden = (float4*)((float*)d_out + (size_t)TOKENS * HIDDEN);

    allreduce_rmsnorm_kernel<<<TOKENS, NTHREADS>>>(
        input, residual, weight, out_norm, out_hidden);
}